// round 10
// baseline (speedup 1.0000x reference)
#include <cuda_runtime.h>
#include <cuda_bf16.h>
#include <cstdint>

// CrossAttentionFusion: B=4, S2_CH=256, DEM_CH=64, OUT_CH=256, H=W=64, N=4096
#define BB 4
#define CS 256
#define CD 64
#define CO 256
#define NN 4096
#define SCALE 0.0625f
#define NJB 32            // number of 128-wide j blocks

// Scratch (device globals: allocation-free rule)
__device__ float         g_Qf[(size_t)BB * CO * NN];
__device__ float         g_Kf[(size_t)BB * CO * NN];
__device__ float         g_Vf[(size_t)BB * CO * NN];
__device__ __nv_bfloat16 g_Qt[(size_t)BB * NN * CO];   // Q^T bf16 [b][j][c] (scale folded)
__device__ __nv_bfloat16 g_Kt[(size_t)BB * NN * CO];   // K^T bf16 [b][i][c]
__device__ __nv_bfloat16 g_Vb[(size_t)BB * CO * NN];   // V' = V/R bf16 [b][c][i]
__device__ __nv_bfloat16 g_E [(size_t)BB * NN * NN];   // exp(logits) bf16 [b][i][j]
__device__ float         g_Rp[(size_t)BB * NJB * NN];  // partial row sums [b][jblk][i]
__device__ float         g_R [(size_t)BB * NN];        // row sums of E

// ===========================================================================
// helpers
// ===========================================================================
__device__ __forceinline__ uint32_t smem_u32(const void* p) {
    uint32_t a;
    asm("{ .reg .u64 t; cvta.to.shared.u64 t, %1; cvt.u32.u64 %0, t; }"
        : "=r"(a) : "l"(p));
    return a;
}

#define CP16(dst, src) \
    asm volatile("cp.async.cg.shared.global [%0], [%1], 16;" \
                 :: "r"(dst), "l"(src))
#define CP_COMMIT() asm volatile("cp.async.commit_group;" ::: "memory")
#define CP_WAIT1()  asm volatile("cp.async.wait_group 1;" ::: "memory")
#define CP_WAIT0()  asm volatile("cp.async.wait_group 0;" ::: "memory")

#define MMA_BF16(d, av, bv) \
    asm volatile("mma.sync.aligned.m16n8k16.row.col.f32.bf16.bf16.f32 " \
                 "{%0,%1,%2,%3}, {%4,%5,%6,%7}, {%8,%9}, {%0,%1,%2,%3};" \
                 : "+f"((d)[0]), "+f"((d)[1]), "+f"((d)[2]), "+f"((d)[3]) \
                 : "r"((av)[0]), "r"((av)[1]), "r"((av)[2]), "r"((av)[3]), \
                   "r"((bv)[0]), "r"((bv)[1]))

__device__ __forceinline__ uint2 pack4bf(float a, float b, float c, float d) {
    __nv_bfloat162 lo = __floats2bfloat162_rn(a, b);
    __nv_bfloat162 hi = __floats2bfloat162_rn(c, d);
    uint2 r;
    r.x = *(uint32_t*)&lo;
    r.y = *(uint32_t*)&hi;
    return r;
}

// ===========================================================================
// s_mma_d: E[b,i,j] = exp( sum_c Kt[b,i,c] * Qt[b,j,c] )   (scale in Qt)
// CTA 128(i) x 128(j), 8 warps (warp tile 64x32), k-chunks of 32, 2-stage.
// Epilogue also emits per-CTA partial row sums -> g_Rp[b][jblk][i].
// ===========================================================================
#define SA_STRIDE 80                       // 32 bf16 (64B) + 16B pad
#define SA_BYTES  (128 * SA_STRIDE)        // 10240
#define S_STAGE   (2 * SA_BYTES)

__global__ void __launch_bounds__(256, 1)
s_mma_d(const __nv_bfloat16* __restrict__ Kt,
        const __nv_bfloat16* __restrict__ Qt,
        __nv_bfloat16* __restrict__ E,
        float* __restrict__ Rp)
{
    __shared__ __align__(16) char sm[2 * S_STAGE];   // 40 KB
    __shared__ float ps[128][4];                     // partial sums per (row, wn)
    const int tid = threadIdx.x, lane = tid & 31, wid = tid >> 5;
    const int b = blockIdx.z, i0 = blockIdx.y * 128, j0 = blockIdx.x * 128;
    const int jblk = blockIdx.x;
    const int wm = wid & 1, wn = wid >> 1;
    const int qr = lane >> 2;
    const int qk = (lane & 3) * 2;

    const __nv_bfloat16* Ag = Kt + ((size_t)b * NN + i0) * CS;
    const __nv_bfloat16* Bg = Qt + ((size_t)b * NN + j0) * CS;
    const uint32_t sbase = smem_u32(sm);

    const int crow = tid >> 2, cseg = tid & 3;

    auto issue = [&](int ch, int st) {
        uint32_t sA = sbase + st * S_STAGE;
        uint32_t sB = sA + SA_BYTES;
        const __nv_bfloat16* a0 = Ag + ch * 32;
        const __nv_bfloat16* b0 = Bg + ch * 32;
        #pragma unroll
        for (int t = 0; t < 2; t++) {
            int row = crow + t * 64;
            uint32_t off = (uint32_t)(row * SA_STRIDE + cseg * 16);
            CP16(sA + off, a0 + (size_t)row * CS + cseg * 8);
            CP16(sB + off, b0 + (size_t)row * CS + cseg * 8);
        }
        CP_COMMIT();
    };

    float acc[4][4][4] = {};
    issue(0, 0);
    issue(1, 1);

    #pragma unroll 1
    for (int ch = 0; ch < 8; ch++) {
        const int st = ch & 1;
        if (ch == 7) CP_WAIT0(); else CP_WAIT1();
        __syncthreads();
        const char* pA = sm + st * S_STAGE;
        const char* pB = pA + SA_BYTES;
        #pragma unroll
        for (int ks = 0; ks < 2; ks++) {
            const int kbyte = ks * 32 + qk * 2;
            uint32_t a[4][4], bb[4][2];
            #pragma unroll
            for (int mf = 0; mf < 4; mf++) {
                int r = wm * 64 + mf * 16 + qr;
                const char* base = pA + r * SA_STRIDE + kbyte;
                a[mf][0] = *(const uint32_t*)(base);
                a[mf][1] = *(const uint32_t*)(base + 8 * SA_STRIDE);
                a[mf][2] = *(const uint32_t*)(base + 16);
                a[mf][3] = *(const uint32_t*)(base + 8 * SA_STRIDE + 16);
            }
            #pragma unroll
            for (int nf = 0; nf < 4; nf++) {
                int n = wn * 32 + nf * 8 + qr;
                const char* base = pB + n * SA_STRIDE + kbyte;
                bb[nf][0] = *(const uint32_t*)(base);
                bb[nf][1] = *(const uint32_t*)(base + 16);
            }
            #pragma unroll
            for (int mf = 0; mf < 4; mf++)
                #pragma unroll
                for (int nf = 0; nf < 4; nf++)
                    MMA_BF16(acc[mf][nf], a[mf], bb[nf]);
        }
        __syncthreads();
        if (ch + 2 < 8) issue(ch + 2, st);
    }

    // Epilogue: exp -> bf16 store; accumulate row sums of the ROUNDED values.
    const int qc = (lane & 3) * 2;
    __nv_bfloat16* Eb = E + ((size_t)b * NN + i0) * NN + j0;
    #pragma unroll
    for (int mf = 0; mf < 4; mf++) {
        float s0 = 0.0f, s1 = 0.0f;   // rows r and r+8, this warp's 32-col slice
        #pragma unroll
        for (int nf = 0; nf < 4; nf++) {
            int r = wm * 64 + mf * 16 + qr;
            int c = wn * 32 + nf * 8 + qc;
            __nv_bfloat162 h0 = __floats2bfloat162_rn(__expf(acc[mf][nf][0]),
                                                      __expf(acc[mf][nf][1]));
            __nv_bfloat162 h1 = __floats2bfloat162_rn(__expf(acc[mf][nf][2]),
                                                      __expf(acc[mf][nf][3]));
            *(__nv_bfloat162*)&Eb[(size_t)r * NN + c] = h0;
            *(__nv_bfloat162*)&Eb[(size_t)(r + 8) * NN + c] = h1;
            float2 f0 = __bfloat1622float2(h0);
            float2 f1 = __bfloat1622float2(h1);
            s0 += f0.x + f0.y;
            s1 += f1.x + f1.y;
        }
        // reduce across the 4 lanes of this row quad (lane&3)
        s0 += __shfl_xor_sync(0xFFFFFFFFu, s0, 1);
        s0 += __shfl_xor_sync(0xFFFFFFFFu, s0, 2);
        s1 += __shfl_xor_sync(0xFFFFFFFFu, s1, 1);
        s1 += __shfl_xor_sync(0xFFFFFFFFu, s1, 2);
        if ((lane & 3) == 0) {
            ps[wm * 64 + mf * 16 + qr][wn] = s0;
            ps[wm * 64 + mf * 16 + qr + 8][wn] = s1;
        }
    }
    __syncthreads();
    if (tid < 128) {
        float t = ps[tid][0] + ps[tid][1] + ps[tid][2] + ps[tid][3];
        Rp[((size_t)b * NJB + jblk) * NN + i0 + tid] = t;
    }
}

// ===========================================================================
// rp_reduce: R[b,i] = sum_jblk Rp[b][jblk][i]
// ===========================================================================
__global__ void rp_reduce_kernel(const float* __restrict__ Rp,
                                 float* __restrict__ R)
{
    const int b = blockIdx.y;
    const int i = blockIdx.x * 256 + threadIdx.x;
    float s = 0.0f;
    #pragma unroll
    for (int jb = 0; jb < NJB; jb++)
        s += Rp[((size_t)b * NJB + jb) * NN + i];
    R[(size_t)b * NN + i] = s;
}

// ===========================================================================
// vscale: Vb[b,c,i] = bf16( Vf[b,c,i] / R[b,i] )
// ===========================================================================
__global__ void vscale_kernel(const float* __restrict__ Vf,
                              const float* __restrict__ R,
                              __nv_bfloat16* __restrict__ Vb)
{
    size_t idx = ((size_t)blockIdx.x * 256 + threadIdx.x) * 4;
    int i = (int)(idx & (NN - 1));
    int b = (int)(idx >> 20);                 // CO*NN = 2^20
    float4 v = *(const float4*)&Vf[idx];
    float4 rr = *(const float4*)&R[(size_t)b * NN + i];
    *(uint2*)&Vb[idx] = pack4bf(v.x / rr.x, v.y / rr.y, v.z / rr.z, v.w / rr.w);
}

// ===========================================================================
// out_mma_d (R6-proven): out[b,c,j] = sum_i V'[b,c,i]*E[b,i,j] + xs2
// 256 threads, CTA 128(c) x 128(j). B-fragments via direct u16 gather.
// ===========================================================================
#define SBO_STRIDE 272                     // 128 bf16 (256B) + 16B pad
#define SBO_BYTES  (32 * SBO_STRIDE)       // 8704
#define O_STAGE    (SA_BYTES + SBO_BYTES)  // 18944

__global__ void __launch_bounds__(256, 1)
out_mma_d(const __nv_bfloat16* __restrict__ V,
          const __nv_bfloat16* __restrict__ E,
          const float* __restrict__ xs2,
          float* __restrict__ out)
{
    __shared__ __align__(16) char sm[2 * O_STAGE];   // 37.9 KB
    const int tid = threadIdx.x, lane = tid & 31, wid = tid >> 5;
    const int b = blockIdx.z, c0 = blockIdx.y * 128, j0 = blockIdx.x * 128;
    const int wm = wid & 1, wn = wid >> 1;
    const int qr = lane >> 2;
    const int qk = (lane & 3) * 2;

    const __nv_bfloat16* Ag = V + ((size_t)b * CO + c0) * NN;
    const __nv_bfloat16* Bg = E + (size_t)b * NN * NN + j0;
    const uint32_t sbase = smem_u32(sm);

    const int arow = tid >> 2, aseg = tid & 3;
    const int brow = tid >> 4, bseg = tid & 15;

    auto issue = [&](int ch, int st) {
        uint32_t sA = sbase + st * O_STAGE;
        uint32_t sB = sA + SA_BYTES;
        const __nv_bfloat16* a0 = Ag + ch * 32;
        const __nv_bfloat16* b0 = Bg + (size_t)(ch * 32) * NN;
        #pragma unroll
        for (int t = 0; t < 2; t++) {
            int ra = arow + t * 64;
            CP16(sA + (uint32_t)(ra * SA_STRIDE + aseg * 16),
                 a0 + (size_t)ra * NN + aseg * 8);
            int rb = brow + t * 16;
            CP16(sB + (uint32_t)(rb * SBO_STRIDE + bseg * 16),
                 b0 + (size_t)rb * NN + bseg * 8);
        }
        CP_COMMIT();
    };

    float acc[4][4][4] = {};
    issue(0, 0);
    issue(1, 1);

    const int NCH = NN / 32;   // 128
    #pragma unroll 1
    for (int ch = 0; ch < NCH; ch++) {
        const int st = ch & 1;
        if (ch == NCH - 1) CP_WAIT0(); else CP_WAIT1();
        __syncthreads();
        const char* pA = sm + st * O_STAGE;
        const char* pB = pA + SA_BYTES;
        #pragma unroll
        for (int ks = 0; ks < 2; ks++) {
            const int kbyteA = ks * 32 + qk * 2;
            uint32_t a[4][4], bb[4][2];
            #pragma unroll
            for (int mf = 0; mf < 4; mf++) {
                int r = wm * 64 + mf * 16 + qr;
                const char* base = pA + r * SA_STRIDE + kbyteA;
                a[mf][0] = *(const uint32_t*)(base);
                a[mf][1] = *(const uint32_t*)(base + 8 * SA_STRIDE);
                a[mf][2] = *(const uint32_t*)(base + 16);
                a[mf][3] = *(const uint32_t*)(base + 8 * SA_STRIDE + 16);
            }
            #pragma unroll
            for (int nf = 0; nf < 4; nf++) {
                int n = wn * 32 + nf * 8 + qr;
                const char* colp = pB + (size_t)(ks * 16 + qk) * SBO_STRIDE + n * 2;
                uint32_t p0 = *(const uint16_t*)(colp);
                uint32_t p1 = *(const uint16_t*)(colp + SBO_STRIDE);
                uint32_t p2 = *(const uint16_t*)(colp + 8 * SBO_STRIDE);
                uint32_t p3 = *(const uint16_t*)(colp + 9 * SBO_STRIDE);
                bb[nf][0] = p0 | (p1 << 16);
                bb[nf][1] = p2 | (p3 << 16);
            }
            #pragma unroll
            for (int mf = 0; mf < 4; mf++)
                #pragma unroll
                for (int nf = 0; nf < 4; nf++)
                    MMA_BF16(acc[mf][nf], a[mf], bb[nf]);
        }
        __syncthreads();
        if (ch + 2 < NCH) issue(ch + 2, st);
    }

    const int qc = (lane & 3) * 2;
    const float* Xb = xs2 + ((size_t)b * CO + c0) * NN + j0;
    float* Ob = out + ((size_t)b * CO + c0) * NN + j0;
    #pragma unroll
    for (int mf = 0; mf < 4; mf++) {
        #pragma unroll
        for (int nf = 0; nf < 4; nf++) {
            int r = wm * 64 + mf * 16 + qr;
            int c = wn * 32 + nf * 8 + qc;
            float2 x0 = *(const float2*)&Xb[(size_t)r * NN + c];
            float2 x1 = *(const float2*)&Xb[(size_t)(r + 8) * NN + c];
            *(float2*)&Ob[(size_t)r * NN + c] =
                make_float2(acc[mf][nf][0] + x0.x, acc[mf][nf][1] + x0.y);
            *(float2*)&Ob[(size_t)(r + 8) * NN + c] =
                make_float2(acc[mf][nf][2] + x1.x, acc[mf][nf][3] + x1.y);
        }
    }
}

// ===========================================================================
// Projection (R1-proven, f32 out)
// ===========================================================================
template <int CIN>
__global__ void proj_kernel(const float* __restrict__ X,
                            const float* __restrict__ W,
                            const float* __restrict__ bias,
                            float* __restrict__ Y)
{
    const int b  = blockIdx.z;
    const int j0 = blockIdx.x * 64;
    const int m0 = blockIdx.y * 64;

    __shared__ float As[16][68];
    __shared__ float Bs[16][68];

    const int tid = threadIdx.x;
    const int tx = tid & 15;
    const int ty = tid >> 4;

    const float* Xb = X + (size_t)b * CIN * NN;
    float acc[4][4] = {};

    for (int k0 = 0; k0 < CIN; k0 += 16) {
        {
            int m  = tid >> 2;
            int kq = (tid & 3) * 4;
            float4 w4 = *(const float4*)&W[(size_t)(m0 + m) * CIN + k0 + kq];
            As[kq + 0][m] = w4.x; As[kq + 1][m] = w4.y;
            As[kq + 2][m] = w4.z; As[kq + 3][m] = w4.w;
        }
        {
            int k  = tid >> 4;
            int jq = (tid & 15) * 4;
            *(float4*)&Bs[k][jq] = *(const float4*)&Xb[(size_t)(k0 + k) * NN + j0 + jq];
        }
        __syncthreads();
        #pragma unroll
        for (int k = 0; k < 16; k++) {
            float4 a4 = *(const float4*)&As[k][ty * 4];
            float4 b4 = *(const float4*)&Bs[k][tx * 4];
            float a[4] = {a4.x, a4.y, a4.z, a4.w};
            float bv[4] = {b4.x, b4.y, b4.z, b4.w};
            #pragma unroll
            for (int i = 0; i < 4; i++)
                #pragma unroll
                for (int j = 0; j < 4; j++)
                    acc[i][j] += a[i] * bv[j];
        }
        __syncthreads();
    }

    float* Yb = Y + (size_t)b * CO * NN;
    #pragma unroll
    for (int i = 0; i < 4; i++) {
        int m = m0 + ty * 4 + i;
        float bs = bias[m];
        *(float4*)&Yb[(size_t)m * NN + j0 + tx * 4] =
            make_float4(acc[i][0] + bs, acc[i][1] + bs,
                        acc[i][2] + bs, acc[i][3] + bs);
    }
}

// ===========================================================================
// Tiled transpose + scale + bf16: Yt[b][n][c] = bf16(X[b][c][n] * scale)
// ===========================================================================
__global__ void transpose_scale_bf16(const float* __restrict__ X,
                                     __nv_bfloat16* __restrict__ Yt,
                                     float scale)
{
    __shared__ float t[32][33];
    const int b  = blockIdx.z;
    const int n0 = blockIdx.x * 32;
    const int c0 = blockIdx.y * 32;
    const int tx = threadIdx.x, ty = threadIdx.y;

    const float* Xb = X + ((size_t)b * CO + c0) * NN + n0;
    #pragma unroll
    for (int k = 0; k < 4; k++) {
        int r = ty + k * 8;
        t[r][tx] = Xb[(size_t)r * NN + tx];
    }
    __syncthreads();

    __nv_bfloat16* Yb = Yt + ((size_t)b * NN + n0) * CO + c0;
    #pragma unroll
    for (int k = 0; k < 4; k++) {
        int r = ty + k * 8;
        Yb[(size_t)r * CO + tx] = __float2bfloat16(t[tx][r] * scale);
    }
}

// ===========================================================================
extern "C" void kernel_launch(void* const* d_in, const int* in_sizes, int n_in,
                              void* d_out, int out_size)
{
    const float* x_s2  = (const float*)d_in[0];
    const float* x_dem = (const float*)d_in[1];
    const float* Wq    = (const float*)d_in[2];
    const float* bq    = (const float*)d_in[3];
    const float* Wk    = (const float*)d_in[4];
    const float* bk    = (const float*)d_in[5];
    const float* Wv    = (const float*)d_in[6];
    const float* bv    = (const float*)d_in[7];
    float* out = (float*)d_out;

    float *Qf, *Kf, *Vf, *Rpp, *Rp2;
    __nv_bfloat16 *Qt, *Kt, *Vb, *Ep;
    cudaGetSymbolAddress((void**)&Qf, g_Qf);
    cudaGetSymbolAddress((void**)&Kf, g_Kf);
    cudaGetSymbolAddress((void**)&Vf, g_Vf);
    cudaGetSymbolAddress((void**)&Qt, g_Qt);
    cudaGetSymbolAddress((void**)&Kt, g_Kt);
    cudaGetSymbolAddress((void**)&Vb, g_Vb);
    cudaGetSymbolAddress((void**)&Ep, g_E);
    cudaGetSymbolAddress((void**)&Rpp, g_Rp);
    cudaGetSymbolAddress((void**)&Rp2, g_R);

    dim3 blk(256);
    dim3 grid_proj(NN / 64, CO / 64, BB);
    proj_kernel<CS><<<grid_proj, blk>>>(x_s2,  Wq, bq, Qf);
    proj_kernel<CD><<<grid_proj, blk>>>(x_dem, Wk, bk, Kf);
    proj_kernel<CD><<<grid_proj, blk>>>(x_dem, Wv, bv, Vf);

    dim3 grid_tr(NN / 32, CO / 32, BB);
    dim3 blk_tr(32, 8);
    transpose_scale_bf16<<<grid_tr, blk_tr>>>(Qf, Qt, SCALE);
    transpose_scale_bf16<<<grid_tr, blk_tr>>>(Kf, Kt, 1.0f);

    s_mma_d<<<dim3(NN / 128, NN / 128, BB), blk>>>(Kt, Qt, Ep, Rpp);

    rp_reduce_kernel<<<dim3(NN / 256, BB), blk>>>(Rpp, Rp2);

    vscale_kernel<<<(unsigned)((size_t)BB * CO * NN / 1024), 256>>>(Vf, Rp2, Vb);

    out_mma_d<<<dim3(NN / 128, CO / 128, BB), blk>>>(Vb, Ep, x_s2, out);
}

// round 11
// speedup vs baseline: 1.0863x; 1.0863x over previous
#include <cuda_runtime.h>
#include <cuda_bf16.h>
#include <cstdint>

// CrossAttentionFusion: B=4, S2_CH=256, DEM_CH=64, OUT_CH=256, H=W=64, N=4096
#define BB 4
#define CS 256
#define CD 64
#define CO 256
#define NN 4096
#define SCALE 0.0625f

// Scratch (device globals: allocation-free rule)
__device__ float         g_Qf[(size_t)BB * CO * NN];
__device__ float         g_Kf[(size_t)BB * CO * NN];
__device__ float         g_Vf[(size_t)BB * CO * NN];
__device__ __nv_bfloat16 g_Qt[(size_t)BB * NN * CO];   // Q^T bf16 [b][j][c] (scale folded)
__device__ __nv_bfloat16 g_Kt[(size_t)BB * NN * CO];   // K^T bf16 [b][i][c]
__device__ __nv_bfloat16 g_Vb[(size_t)BB * CO * NN];   // V' = V/R bf16 [b][c][i]
__device__ __nv_bfloat16 g_E [(size_t)BB * NN * NN];   // exp(logits) bf16 [b][i][j]
__device__ float         g_R [(size_t)BB * NN];        // row sums of E

// ===========================================================================
// helpers
// ===========================================================================
__device__ __forceinline__ uint32_t smem_u32(const void* p) {
    uint32_t a;
    asm("{ .reg .u64 t; cvta.to.shared.u64 t, %1; cvt.u32.u64 %0, t; }"
        : "=r"(a) : "l"(p));
    return a;
}

#define CP16(dst, src) \
    asm volatile("cp.async.cg.shared.global [%0], [%1], 16;" \
                 :: "r"(dst), "l"(src))
#define CP_COMMIT() asm volatile("cp.async.commit_group;" ::: "memory")
#define CP_WAIT1()  asm volatile("cp.async.wait_group 1;" ::: "memory")
#define CP_WAIT0()  asm volatile("cp.async.wait_group 0;" ::: "memory")

#define LDSM2T(r0, r1, addr) \
    asm volatile("ldmatrix.sync.aligned.m8n8.x2.trans.shared.b16 {%0,%1}, [%2];" \
                 : "=r"(r0), "=r"(r1) : "r"(addr))

#define MMA_BF16(d, av, bv) \
    asm volatile("mma.sync.aligned.m16n8k16.row.col.f32.bf16.bf16.f32 " \
                 "{%0,%1,%2,%3}, {%4,%5,%6,%7}, {%8,%9}, {%0,%1,%2,%3};" \
                 : "+f"((d)[0]), "+f"((d)[1]), "+f"((d)[2]), "+f"((d)[3]) \
                 : "r"((av)[0]), "r"((av)[1]), "r"((av)[2]), "r"((av)[3]), \
                   "r"((bv)[0]), "r"((bv)[1]))

__device__ __forceinline__ uint2 pack4bf(float a, float b, float c, float d) {
    __nv_bfloat162 lo = __floats2bfloat162_rn(a, b);
    __nv_bfloat162 hi = __floats2bfloat162_rn(c, d);
    uint2 r;
    r.x = *(uint32_t*)&lo;
    r.y = *(uint32_t*)&hi;
    return r;
}

// ===========================================================================
// s_mma_d: E[b,i,j] = exp( sum_c Kt[b,i,c] * Qt[b,j,c] )   (scale in Qt)
// CTA 128(i) x 128(j), 8 warps (warp tile 64x32), k-chunks of 32, 2-stage.
// (R6-proven: simple epilogue, no fused row sums.)
// ===========================================================================
#define SA_STRIDE 80                       // 32 bf16 (64B) + 16B pad
#define SA_BYTES  (128 * SA_STRIDE)        // 10240
#define S_STAGE   (2 * SA_BYTES)

__global__ void __launch_bounds__(256, 1)
s_mma_d(const __nv_bfloat16* __restrict__ Kt,
        const __nv_bfloat16* __restrict__ Qt,
        __nv_bfloat16* __restrict__ E)
{
    __shared__ __align__(16) char sm[2 * S_STAGE];   // 40 KB
    const int tid = threadIdx.x, lane = tid & 31, wid = tid >> 5;
    const int b = blockIdx.z, i0 = blockIdx.y * 128, j0 = blockIdx.x * 128;
    const int wm = wid & 1, wn = wid >> 1;
    const int qr = lane >> 2;
    const int qk = (lane & 3) * 2;

    const __nv_bfloat16* Ag = Kt + ((size_t)b * NN + i0) * CS;
    const __nv_bfloat16* Bg = Qt + ((size_t)b * NN + j0) * CS;
    const uint32_t sbase = smem_u32(sm);

    const int crow = tid >> 2, cseg = tid & 3;

    auto issue = [&](int ch, int st) {
        uint32_t sA = sbase + st * S_STAGE;
        uint32_t sB = sA + SA_BYTES;
        const __nv_bfloat16* a0 = Ag + ch * 32;
        const __nv_bfloat16* b0 = Bg + ch * 32;
        #pragma unroll
        for (int t = 0; t < 2; t++) {
            int row = crow + t * 64;
            uint32_t off = (uint32_t)(row * SA_STRIDE + cseg * 16);
            CP16(sA + off, a0 + (size_t)row * CS + cseg * 8);
            CP16(sB + off, b0 + (size_t)row * CS + cseg * 8);
        }
        CP_COMMIT();
    };

    float acc[4][4][4] = {};
    issue(0, 0);
    issue(1, 1);

    #pragma unroll 1
    for (int ch = 0; ch < 8; ch++) {
        const int st = ch & 1;
        if (ch == 7) CP_WAIT0(); else CP_WAIT1();
        __syncthreads();
        const char* pA = sm + st * S_STAGE;
        const char* pB = pA + SA_BYTES;
        #pragma unroll
        for (int ks = 0; ks < 2; ks++) {
            const int kbyte = ks * 32 + qk * 2;
            uint32_t a[4][4], bb[4][2];
            #pragma unroll
            for (int mf = 0; mf < 4; mf++) {
                int r = wm * 64 + mf * 16 + qr;
                const char* base = pA + r * SA_STRIDE + kbyte;
                a[mf][0] = *(const uint32_t*)(base);
                a[mf][1] = *(const uint32_t*)(base + 8 * SA_STRIDE);
                a[mf][2] = *(const uint32_t*)(base + 16);
                a[mf][3] = *(const uint32_t*)(base + 8 * SA_STRIDE + 16);
            }
            #pragma unroll
            for (int nf = 0; nf < 4; nf++) {
                int n = wn * 32 + nf * 8 + qr;
                const char* base = pB + n * SA_STRIDE + kbyte;
                bb[nf][0] = *(const uint32_t*)(base);
                bb[nf][1] = *(const uint32_t*)(base + 16);
            }
            #pragma unroll
            for (int mf = 0; mf < 4; mf++)
                #pragma unroll
                for (int nf = 0; nf < 4; nf++)
                    MMA_BF16(acc[mf][nf], a[mf], bb[nf]);
        }
        __syncthreads();
        if (ch + 2 < 8) issue(ch + 2, st);
    }

    const int qc = (lane & 3) * 2;
    __nv_bfloat16* Eb = E + ((size_t)b * NN + i0) * NN + j0;
    #pragma unroll
    for (int mf = 0; mf < 4; mf++) {
        #pragma unroll
        for (int nf = 0; nf < 4; nf++) {
            int r = wm * 64 + mf * 16 + qr;
            int c = wn * 32 + nf * 8 + qc;
            *(__nv_bfloat162*)&Eb[(size_t)r * NN + c] =
                __floats2bfloat162_rn(__expf(acc[mf][nf][0]), __expf(acc[mf][nf][1]));
            *(__nv_bfloat162*)&Eb[(size_t)(r + 8) * NN + c] =
                __floats2bfloat162_rn(__expf(acc[mf][nf][2]), __expf(acc[mf][nf][3]));
        }
    }
}

// ===========================================================================
// rowsum: R[b,i] = sum_j E[b,i,j]   (f32 accumulate from stored bf16 E)
// ===========================================================================
__global__ void rowsum_kernel(const __nv_bfloat16* __restrict__ E,
                              float* __restrict__ R)
{
    const int i = blockIdx.x, b = blockIdx.y;
    const uint4* row = (const uint4*)(E + ((size_t)b * NN + i) * NN);
    const int tid = threadIdx.x;
    __shared__ float red[8];

    float s = 0.0f;
    #pragma unroll
    for (int u = 0; u < 2; u++) {
        uint4 v = row[tid + u * 256];
        uint32_t w[4] = {v.x, v.y, v.z, v.w};
        #pragma unroll
        for (int q = 0; q < 4; q++) {
            float2 f = __bfloat1622float2(*(const __nv_bfloat162*)&w[q]);
            s += f.x + f.y;
        }
    }
    #pragma unroll
    for (int off = 16; off > 0; off >>= 1)
        s += __shfl_xor_sync(0xFFFFFFFFu, s, off);
    if ((tid & 31) == 0) red[tid >> 5] = s;
    __syncthreads();
    if (tid == 0) {
        float t = 0.0f;
        #pragma unroll
        for (int w2 = 0; w2 < 8; w2++) t += red[w2];
        R[(size_t)b * NN + i] = t;
    }
}

// ===========================================================================
// vscale: Vb[b,c,i] = bf16( Vf[b,c,i] / R[b,i] )
// ===========================================================================
__global__ void vscale_kernel(const float* __restrict__ Vf,
                              const float* __restrict__ R,
                              __nv_bfloat16* __restrict__ Vb)
{
    size_t idx = ((size_t)blockIdx.x * 256 + threadIdx.x) * 4;
    int i = (int)(idx & (NN - 1));
    int b = (int)(idx >> 20);                 // CO*NN = 2^20
    float4 v = *(const float4*)&Vf[idx];
    float4 rr = *(const float4*)&R[(size_t)b * NN + i];
    *(uint2*)&Vb[idx] = pack4bf(v.x / rr.x, v.y / rr.y, v.z / rr.z, v.w / rr.w);
}

// ===========================================================================
// out_mma_d: out[b,c,j] = sum_i V'[b,c,i]*E[b,i,j] + xs2
// 256 threads, CTA 128(c) x 128(j). B-fragments via ldmatrix.x2.trans
// (R7-proven correct, ~-9us vs u16 gather).
// ===========================================================================
#define SBO_STRIDE 272                     // 128 bf16 (256B) + 16B pad
#define SBO_BYTES  (32 * SBO_STRIDE)       // 8704
#define O_STAGE    (SA_BYTES + SBO_BYTES)  // 18944

__global__ void __launch_bounds__(256, 1)
out_mma_d(const __nv_bfloat16* __restrict__ V,
          const __nv_bfloat16* __restrict__ E,
          const float* __restrict__ xs2,
          float* __restrict__ out)
{
    __shared__ __align__(16) char sm[2 * O_STAGE];   // 37.9 KB
    const int tid = threadIdx.x, lane = tid & 31, wid = tid >> 5;
    const int b = blockIdx.z, c0 = blockIdx.y * 128, j0 = blockIdx.x * 128;
    const int wm = wid & 1, wn = wid >> 1;
    const int qr = lane >> 2;
    const int qk = (lane & 3) * 2;
    const int ln = lane & 15;

    const __nv_bfloat16* Ag = V + ((size_t)b * CO + c0) * NN;
    const __nv_bfloat16* Bg = E + (size_t)b * NN * NN + j0;
    const uint32_t sbase = smem_u32(sm);

    const int arow = tid >> 2, aseg = tid & 3;
    const int brow = tid >> 4, bseg = tid & 15;

    auto issue = [&](int ch, int st) {
        uint32_t sA = sbase + st * O_STAGE;
        uint32_t sB = sA + SA_BYTES;
        const __nv_bfloat16* a0 = Ag + ch * 32;
        const __nv_bfloat16* b0 = Bg + (size_t)(ch * 32) * NN;
        #pragma unroll
        for (int t = 0; t < 2; t++) {
            int ra = arow + t * 64;
            CP16(sA + (uint32_t)(ra * SA_STRIDE + aseg * 16),
                 a0 + (size_t)ra * NN + aseg * 8);
            int rb = brow + t * 16;
            CP16(sB + (uint32_t)(rb * SBO_STRIDE + bseg * 16),
                 b0 + (size_t)rb * NN + bseg * 8);
        }
        CP_COMMIT();
    };

    float acc[4][4][4] = {};
    issue(0, 0);
    issue(1, 1);

    const int NCH = NN / 32;   // 128
    #pragma unroll 1
    for (int ch = 0; ch < NCH; ch++) {
        const int st = ch & 1;
        if (ch == NCH - 1) CP_WAIT0(); else CP_WAIT1();
        __syncthreads();
        const char* pA = sm + st * O_STAGE;
        const uint32_t sB32 = sbase + st * O_STAGE + SA_BYTES;
        #pragma unroll
        for (int ks = 0; ks < 2; ks++) {
            const int kbyteA = ks * 32 + qk * 2;
            // ldmatrix.trans row addresses: rows k = ks*16 + ln (lanes 0-15)
            const uint32_t brow_addr = sB32 + (uint32_t)((ks * 16 + ln) * SBO_STRIDE
                                                         + wn * 64);
            uint32_t a[4][4], bb[4][2];
            #pragma unroll
            for (int mf = 0; mf < 4; mf++) {
                int r = wm * 64 + mf * 16 + qr;
                const char* base = pA + r * SA_STRIDE + kbyteA;
                a[mf][0] = *(const uint32_t*)(base);
                a[mf][1] = *(const uint32_t*)(base + 8 * SA_STRIDE);
                a[mf][2] = *(const uint32_t*)(base + 16);
                a[mf][3] = *(const uint32_t*)(base + 8 * SA_STRIDE + 16);
            }
            #pragma unroll
            for (int nf = 0; nf < 4; nf++)
                LDSM2T(bb[nf][0], bb[nf][1], brow_addr + nf * 16);
            #pragma unroll
            for (int mf = 0; mf < 4; mf++)
                #pragma unroll
                for (int nf = 0; nf < 4; nf++)
                    MMA_BF16(acc[mf][nf], a[mf], bb[nf]);
        }
        __syncthreads();
        if (ch + 2 < NCH) issue(ch + 2, st);
    }

    const int qc = (lane & 3) * 2;
    const float* Xb = xs2 + ((size_t)b * CO + c0) * NN + j0;
    float* Ob = out + ((size_t)b * CO + c0) * NN + j0;
    #pragma unroll
    for (int mf = 0; mf < 4; mf++) {
        #pragma unroll
        for (int nf = 0; nf < 4; nf++) {
            int r = wm * 64 + mf * 16 + qr;
            int c = wn * 32 + nf * 8 + qc;
            float2 x0 = *(const float2*)&Xb[(size_t)r * NN + c];
            float2 x1 = *(const float2*)&Xb[(size_t)(r + 8) * NN + c];
            *(float2*)&Ob[(size_t)r * NN + c] =
                make_float2(acc[mf][nf][0] + x0.x, acc[mf][nf][1] + x0.y);
            *(float2*)&Ob[(size_t)(r + 8) * NN + c] =
                make_float2(acc[mf][nf][2] + x1.x, acc[mf][nf][3] + x1.y);
        }
    }
}

// ===========================================================================
// Projection (R1-proven, f32 out)
// ===========================================================================
template <int CIN>
__global__ void proj_kernel(const float* __restrict__ X,
                            const float* __restrict__ W,
                            const float* __restrict__ bias,
                            float* __restrict__ Y)
{
    const int b  = blockIdx.z;
    const int j0 = blockIdx.x * 64;
    const int m0 = blockIdx.y * 64;

    __shared__ float As[16][68];
    __shared__ float Bs[16][68];

    const int tid = threadIdx.x;
    const int tx = tid & 15;
    const int ty = tid >> 4;

    const float* Xb = X + (size_t)b * CIN * NN;
    float acc[4][4] = {};

    for (int k0 = 0; k0 < CIN; k0 += 16) {
        {
            int m  = tid >> 2;
            int kq = (tid & 3) * 4;
            float4 w4 = *(const float4*)&W[(size_t)(m0 + m) * CIN + k0 + kq];
            As[kq + 0][m] = w4.x; As[kq + 1][m] = w4.y;
            As[kq + 2][m] = w4.z; As[kq + 3][m] = w4.w;
        }
        {
            int k  = tid >> 4;
            int jq = (tid & 15) * 4;
            *(float4*)&Bs[k][jq] = *(const float4*)&Xb[(size_t)(k0 + k) * NN + j0 + jq];
        }
        __syncthreads();
        #pragma unroll
        for (int k = 0; k < 16; k++) {
            float4 a4 = *(const float4*)&As[k][ty * 4];
            float4 b4 = *(const float4*)&Bs[k][tx * 4];
            float a[4] = {a4.x, a4.y, a4.z, a4.w};
            float bv[4] = {b4.x, b4.y, b4.z, b4.w};
            #pragma unroll
            for (int i = 0; i < 4; i++)
                #pragma unroll
                for (int j = 0; j < 4; j++)
                    acc[i][j] += a[i] * bv[j];
        }
        __syncthreads();
    }

    float* Yb = Y + (size_t)b * CO * NN;
    #pragma unroll
    for (int i = 0; i < 4; i++) {
        int m = m0 + ty * 4 + i;
        float bs = bias[m];
        *(float4*)&Yb[(size_t)m * NN + j0 + tx * 4] =
            make_float4(acc[i][0] + bs, acc[i][1] + bs,
                        acc[i][2] + bs, acc[i][3] + bs);
    }
}

// ===========================================================================
// Tiled transpose + scale + bf16: Yt[b][n][c] = bf16(X[b][c][n] * scale)
// ===========================================================================
__global__ void transpose_scale_bf16(const float* __restrict__ X,
                                     __nv_bfloat16* __restrict__ Yt,
                                     float scale)
{
    __shared__ float t[32][33];
    const int b  = blockIdx.z;
    const int n0 = blockIdx.x * 32;
    const int c0 = blockIdx.y * 32;
    const int tx = threadIdx.x, ty = threadIdx.y;

    const float* Xb = X + ((size_t)b * CO + c0) * NN + n0;
    #pragma unroll
    for (int k = 0; k < 4; k++) {
        int r = ty + k * 8;
        t[r][tx] = Xb[(size_t)r * NN + tx];
    }
    __syncthreads();

    __nv_bfloat16* Yb = Yt + ((size_t)b * NN + n0) * CO + c0;
    #pragma unroll
    for (int k = 0; k < 4; k++) {
        int r = ty + k * 8;
        Yb[(size_t)r * CO + tx] = __float2bfloat16(t[tx][r] * scale);
    }
}

// ===========================================================================
extern "C" void kernel_launch(void* const* d_in, const int* in_sizes, int n_in,
                              void* d_out, int out_size)
{
    const float* x_s2  = (const float*)d_in[0];
    const float* x_dem = (const float*)d_in[1];
    const float* Wq    = (const float*)d_in[2];
    const float* bq    = (const float*)d_in[3];
    const float* Wk    = (const float*)d_in[4];
    const float* bk    = (const float*)d_in[5];
    const float* Wv    = (const float*)d_in[6];
    const float* bv    = (const float*)d_in[7];
    float* out = (float*)d_out;

    float *Qf, *Kf, *Vf, *Rp;
    __nv_bfloat16 *Qt, *Kt, *Vb, *Ep;
    cudaGetSymbolAddress((void**)&Qf, g_Qf);
    cudaGetSymbolAddress((void**)&Kf, g_Kf);
    cudaGetSymbolAddress((void**)&Vf, g_Vf);
    cudaGetSymbolAddress((void**)&Qt, g_Qt);
    cudaGetSymbolAddress((void**)&Kt, g_Kt);
    cudaGetSymbolAddress((void**)&Vb, g_Vb);
    cudaGetSymbolAddress((void**)&Ep, g_E);
    cudaGetSymbolAddress((void**)&Rp, g_R);

    dim3 blk(256);
    dim3 grid_proj(NN / 64, CO / 64, BB);
    proj_kernel<CS><<<grid_proj, blk>>>(x_s2,  Wq, bq, Qf);
    proj_kernel<CD><<<grid_proj, blk>>>(x_dem, Wk, bk, Kf);
    proj_kernel<CD><<<grid_proj, blk>>>(x_dem, Wv, bv, Vf);

    dim3 grid_tr(NN / 32, CO / 32, BB);
    dim3 blk_tr(32, 8);
    transpose_scale_bf16<<<grid_tr, blk_tr>>>(Qf, Qt, SCALE);
    transpose_scale_bf16<<<grid_tr, blk_tr>>>(Kf, Kt, 1.0f);

    s_mma_d<<<dim3(NN / 128, NN / 128, BB), blk>>>(Kt, Qt, Ep);

    rowsum_kernel<<<dim3(NN, BB), blk>>>(Ep, Rp);

    vscale_kernel<<<(unsigned)((size_t)BB * CO * NN / 1024), 256>>>(Vf, Rp, Vb);

    out_mma_d<<<dim3(NN / 128, CO / 128, BB), blk>>>(Vb, Ep, x_s2, out);
}